// round 1
// baseline (speedup 1.0000x reference)
#include <cuda_runtime.h>

// Router: alpha = softmax(topk_mask(z @ W^T + b))
// z: [N=8192, D=4096] f32, W: [K=64, D] f32, b: [K] f32, k: int (=2)
// out: [N, K] f32, nonzero only at top-k positions per row.

namespace {
constexpr int Dc = 4096;
constexpr int Kc = 64;
constexpr int BM = 64;   // rows per CTA
constexpr int BK = 32;   // d-chunk
constexpr int NTHREADS = 256;

__device__ __forceinline__ unsigned long long pk2(float x, float y) {
    unsigned long long r;
    asm("mov.b64 %0, {%1, %2};" : "=l"(r) : "f"(x), "f"(y));
    return r;
}
__device__ __forceinline__ float2 upk2(unsigned long long v) {
    float2 r;
    asm("mov.b64 {%0, %1}, %2;" : "=f"(r.x), "=f"(r.y) : "l"(v));
    return r;
}
// Packed dual-FMA (Blackwell f32x2). d = a*b + d elementwise on packed f32 pairs.
__device__ __forceinline__ void ffma2(unsigned long long& d,
                                      unsigned long long a,
                                      unsigned long long b) {
    asm("fma.rn.f32x2 %0, %1, %2, %3;" : "=l"(d) : "l"(a), "l"(b), "l"(d));
}
} // namespace

__global__ __launch_bounds__(NTHREADS, 1) void router_kernel(
    const float* __restrict__ z, const float* __restrict__ W,
    const float* __restrict__ b, const int* __restrict__ kptr,
    float* __restrict__ out)
{
    // zs: [BM][BK+1] (pad kills LDS bank conflicts on z scalar reads)
    // wsT: [BK][Kc+4] (transposed W chunk; +4 pad keeps float4 alignment & spreads STS banks)
    // epilogue logits overlay: [BM][Kc+1] = 4160 floats <= 4288
    __shared__ float smem[BM * (BK + 1) + BK * (Kc + 4)];
    float* zs  = smem;
    float* wsT = smem + BM * (BK + 1);

    const int tid  = threadIdx.x;
    const int row0 = blockIdx.x * BM;
    const int ty = tid >> 4;   // 0..15 -> 4 rows each
    const int tx = tid & 15;   // 0..15 -> 4 cols each

    unsigned long long acc[4][2];
#pragma unroll
    for (int j = 0; j < 4; ++j) { acc[j][0] = 0ull; acc[j][1] = 0ull; }

    // Each thread loads 2 float4 of z and 2 float4 of W per tile (both tiles 64x32).
    const int f0 = tid, f1 = tid + NTHREADS;
    const int r0i = f0 >> 3, c0i = (f0 & 7) * 4;
    const int r1i = f1 >> 3, c1i = (f1 & 7) * 4;

    float4 pz0, pz1, pw0, pw1;

#define LOAD_TILE(dBase)                                                        \
    do {                                                                        \
        pz0 = *(const float4*)(z + (size_t)(row0 + r0i) * Dc + (dBase) + c0i);  \
        pz1 = *(const float4*)(z + (size_t)(row0 + r1i) * Dc + (dBase) + c1i);  \
        pw0 = *(const float4*)(W + (size_t)r0i * Dc + (dBase) + c0i);           \
        pw1 = *(const float4*)(W + (size_t)r1i * Dc + (dBase) + c1i);           \
    } while (0)

#define STORE_TILE()                                                            \
    do {                                                                        \
        zs[r0i * (BK + 1) + c0i + 0] = pz0.x;                                   \
        zs[r0i * (BK + 1) + c0i + 1] = pz0.y;                                   \
        zs[r0i * (BK + 1) + c0i + 2] = pz0.z;                                   \
        zs[r0i * (BK + 1) + c0i + 3] = pz0.w;                                   \
        zs[r1i * (BK + 1) + c1i + 0] = pz1.x;                                   \
        zs[r1i * (BK + 1) + c1i + 1] = pz1.y;                                   \
        zs[r1i * (BK + 1) + c1i + 2] = pz1.z;                                   \
        zs[r1i * (BK + 1) + c1i + 3] = pz1.w;                                   \
        wsT[(c0i + 0) * (Kc + 4) + r0i] = pw0.x;                                \
        wsT[(c0i + 1) * (Kc + 4) + r0i] = pw0.y;                                \
        wsT[(c0i + 2) * (Kc + 4) + r0i] = pw0.z;                                \
        wsT[(c0i + 3) * (Kc + 4) + r0i] = pw0.w;                                \
        wsT[(c1i + 0) * (Kc + 4) + r1i] = pw1.x;                                \
        wsT[(c1i + 1) * (Kc + 4) + r1i] = pw1.y;                                \
        wsT[(c1i + 2) * (Kc + 4) + r1i] = pw1.z;                                \
        wsT[(c1i + 3) * (Kc + 4) + r1i] = pw1.w;                                \
    } while (0)

    constexpr int T = Dc / BK;  // 128 tiles
    LOAD_TILE(0);
    STORE_TILE();
    __syncthreads();

    for (int t = 0; t < T; ++t) {
        const bool has_next = (t + 1 < T);
        if (has_next) LOAD_TILE((t + 1) * BK);  // LDGs in flight during compute

#pragma unroll
        for (int d = 0; d < BK; ++d) {
            const float a0 = zs[(ty * 4 + 0) * (BK + 1) + d];
            const float a1 = zs[(ty * 4 + 1) * (BK + 1) + d];
            const float a2 = zs[(ty * 4 + 2) * (BK + 1) + d];
            const float a3 = zs[(ty * 4 + 3) * (BK + 1) + d];
            const float4 wv = *(const float4*)(wsT + d * (Kc + 4) + tx * 4);
            const unsigned long long w01 = pk2(wv.x, wv.y);
            const unsigned long long w23 = pk2(wv.z, wv.w);
            unsigned long long A;
            A = pk2(a0, a0); ffma2(acc[0][0], A, w01); ffma2(acc[0][1], A, w23);
            A = pk2(a1, a1); ffma2(acc[1][0], A, w01); ffma2(acc[1][1], A, w23);
            A = pk2(a2, a2); ffma2(acc[2][0], A, w01); ffma2(acc[2][1], A, w23);
            A = pk2(a3, a3); ffma2(acc[3][0], A, w01); ffma2(acc[3][1], A, w23);
        }
        __syncthreads();
        if (has_next) {
            STORE_TILE();
            __syncthreads();
        }
    }

    // ---- Epilogue: logits tile -> top-k mask -> softmax ----
    float* lg = smem;  // [BM][Kc+1]
#pragma unroll
    for (int j = 0; j < 4; ++j) {
        const float2 v0 = upk2(acc[j][0]);
        const float2 v1 = upk2(acc[j][1]);
        const int row = ty * 4 + j;
        const int col = tx * 4;
        lg[row * (Kc + 1) + col + 0] = v0.x + b[col + 0];
        lg[row * (Kc + 1) + col + 1] = v0.y + b[col + 1];
        lg[row * (Kc + 1) + col + 2] = v1.x + b[col + 2];
        lg[row * (Kc + 1) + col + 3] = v1.y + b[col + 3];
    }
    __syncthreads();

    if (tid < BM) {
        int kk = kptr ? *kptr : 2;
        if (kk < 1) kk = 1;
        if (kk > Kc) kk = Kc;

        float* r = lg + tid * (Kc + 1);

        // k passes of argmax; strict '>' keeps lowest index on ties,
        // matching jax.lax.top_k tie-breaking.
        unsigned long long sel = 0ull;
        float m = 0.f;
        for (int p = 0; p < kk; ++p) {
            float best = -3.4e38f;
            int bi = 0;
            for (int c = 0; c < Kc; ++c) {
                const float v = r[c];
                const bool taken = (sel >> c) & 1ull;
                if (!taken && v > best) { best = v; bi = c; }
            }
            sel |= (1ull << bi);
            if (p == 0) m = best;  // max of sparse logits == top-1
        }

        // softmax over sparse logits; non-selected entries are exactly 0,
        // matching expf(logit - max - 1e9) underflow in fp32.
        float sum = 0.f;
        for (int c = 0; c < Kc; ++c) {
            const float e = ((sel >> c) & 1ull) ? expf(r[c] - m) : 0.f;
            r[c] = e;
            sum += e;
        }
        const float inv = 1.0f / sum;
        float* o = out + (size_t)(row0 + tid) * Kc;
        for (int c = 0; c < Kc; ++c) o[c] = r[c] * inv;
    }
#undef LOAD_TILE
#undef STORE_TILE
}

extern "C" void kernel_launch(void* const* d_in, const int* in_sizes, int n_in,
                              void* d_out, int out_size) {
    const float* z = (const float*)d_in[0];
    const float* W = (const float*)d_in[1];
    const float* b = (const float*)d_in[2];
    const int* kp = (n_in > 3) ? (const int*)d_in[3] : nullptr;
    float* out = (float*)d_out;

    const int N = in_sizes[0] / Dc;  // 8192
    router_kernel<<<N / BM, NTHREADS>>>(z, W, b, kp, out);
    (void)out_size;
}